// round 12
// baseline (speedup 1.0000x reference)
#include <cuda_runtime.h>
#include <cuda_fp16.h>
#include <cstdint>

// ---------------- problem constants ----------------
#define T_TOKENS 16384
#define DMODEL   2048
#define NEXP     64
#define MT       32
#define NCTAS    (T_TOKENS / MT)      // 512
#define NTHREADS 256
#define BK       32
#define KT       (DMODEL / BK)        // 64
#define SCALE    2048.0f
#define INVS     (1.0f / 2048.0f)

// ---------------- output layout (fp32, reference return order) ----------------
#define OFF_W    ((size_t)0)
#define OFF_I    ((size_t)32768)
#define OFF_P    ((size_t)65536)
#define OFF_ENT  ((size_t)1114112)
#define OFF_CONF ((size_t)1114113)
#define OFF_UTIL ((size_t)1114114)

// ---------------- smem layout ----------------
// rows padded to 80B: stride mod 128 cycles 8 distinct 16B groups -> conflict-free ldmatrix.
#define RSTR     80
#define AH_OFF   0                      // A: 32 rows x 64B data
#define AM_OFF   (32 * RSTR)            // 2560
#define BH_OFF   (2 * 32 * RSTR)        // 5120   B: 64 rows x 64B data
#define BM_OFF   (BH_OFF + 64 * RSTR)   // 10240
#define BUFG     (BH_OFF + 2 * 64 * RSTR)  // 15360 per buffer
#define DSM_BYTES (2 * BUFG)            // 30720 (double buffer)
#define LSTR     66                      // logits row stride (floats)

// ---------------- device globals ----------------
__device__ __half g_Wh[NEXP * DMODEL];
__device__ __half g_Wm[NEXP * DMODEL];
__device__ float  g_ent;
__device__ float  g_conf;
__device__ int    g_counts[NEXP];
__device__ int    g_done;

// ---------------- helpers ----------------
__device__ __forceinline__ uint32_t smem_u32(const void* p) {
    uint32_t a;
    asm("{ .reg .u64 t; cvta.to.shared.u64 t, %1; cvt.u32.u64 %0, t; }" : "=r"(a) : "l"(p));
    return a;
}
#define STS64(addr, a, b) \
    asm volatile("st.shared.v2.b32 [%0], {%1,%2};" :: "r"(addr), "r"(a), "r"(b) : "memory")
#define CP_ASYNC16(dst, src) \
    asm volatile("cp.async.cg.shared.global [%0], [%1], 16;" :: "r"(dst), "l"(src) : "memory")
#define CP_COMMIT() asm volatile("cp.async.commit_group;" ::: "memory")
#define CP_WAIT0()  asm volatile("cp.async.wait_group 0;" ::: "memory")

__device__ __forceinline__ void ldsm4(uint32_t& r0, uint32_t& r1, uint32_t& r2, uint32_t& r3, uint32_t a) {
    asm volatile("ldmatrix.sync.aligned.m8n8.x4.shared.b16 {%0,%1,%2,%3}, [%4];"
                 : "=r"(r0), "=r"(r1), "=r"(r2), "=r"(r3) : "r"(a));
}
__device__ __forceinline__ void mma16816(float* c, const uint32_t* a, const uint32_t* b) {
    asm volatile("mma.sync.aligned.m16n8k16.row.col.f32.f16.f16.f32 "
                 "{%0,%1,%2,%3},{%4,%5,%6,%7},{%8,%9},{%0,%1,%2,%3};"
                 : "+f"(c[0]), "+f"(c[1]), "+f"(c[2]), "+f"(c[3])
                 : "r"(a[0]), "r"(a[1]), "r"(a[2]), "r"(a[3]), "r"(b[0]), "r"(b[1]));
}

// two-limb fp16 split of a float pair -> packed H and scaled-M half2s
__device__ __forceinline__ void cvt2(float a, float b, uint32_t& H, uint32_t& M) {
    __half2 h = __floats2half2_rn(a, b);
    float2 hf = __half22float2(h);
    __half2 m = __floats2half2_rn((a - hf.x) * SCALE, (b - hf.y) * SCALE);
    H = *reinterpret_cast<uint32_t*>(&h);
    M = *reinterpret_cast<uint32_t*>(&m);
}

// strict ordering with lowest-index tie-break (matches jax top_k)
__device__ __forceinline__ bool ordgt(float a, int ia, float b, int ib) {
    return (a > b) || (a == b && ia < ib);
}

// ---------------- prep: zero stats + split W into fp16 limbs ----------------
__global__ void prep_kernel(const float* __restrict__ W) {
    if (blockIdx.x == 0) {
        if (threadIdx.x == 0) { g_ent = 0.0f; g_conf = 0.0f; g_done = 0; }
        if (threadIdx.x < NEXP) g_counts[threadIdx.x] = 0;
    }
    int i = (blockIdx.x * 256 + threadIdx.x) * 4;
    if (i < NEXP * DMODEL) {
        float4 f = *(const float4*)(W + i);
        uint32_t h0, m0, h1, m1;
        cvt2(f.x, f.y, h0, m0);
        cvt2(f.z, f.w, h1, m1);
        *(uint2*)(g_Wh + i) = make_uint2(h0, h1);
        *(uint2*)(g_Wm + i) = make_uint2(m0, m1);
    }
}

// ---------------- main fused router ----------------
__global__ __launch_bounds__(NTHREADS, 3)
void router_kernel(const float* __restrict__ x, float* __restrict__ out) {
    extern __shared__ __align__(16) char dsm[];
    __shared__ int hist[NEXP];
    __shared__ int s_last;

    const int t    = threadIdx.x;
    const int wid  = t >> 5;
    const int lane = t & 31;
    const int mbase = blockIdx.x * MT;
    const uint32_t smbase = smem_u32(dsm);

    if (t < NEXP) hist[t] = 0;

    // A staging: row = t>>3 (0..31), 4-float chunk = t&7
    const int ar = t >> 3;
    const int ac = t & 7;
    const float* xp = x + (size_t)(mbase + ar) * DMODEL + ac * 4;
    const uint32_t aH = smbase + AH_OFF + (uint32_t)(ar * RSTR + ac * 8);
    const uint32_t aM = smbase + AM_OFF + (uint32_t)(ar * RSTR + ac * 8);

    // B cp.async: row = t>>2 (0..63), 16B chunk = t&3
    const int br = t >> 2;
    const int bc = t & 3;
    const uint32_t bDstH = smbase + BH_OFF + (uint32_t)(br * RSTR + bc * 16);
    const uint32_t bDstM = smbase + BM_OFF + (uint32_t)(br * RSTR + bc * 16);
    const __half* bSrcH = g_Wh + (size_t)br * DMODEL + bc * 8;
    const __half* bSrcM = g_Wm + (size_t)br * DMODEL + bc * 8;

    // warps: 4n x 2k; each M32 x N16, k16
    const int ks = wid >> 2;
    const int wn = (wid & 3) * 16;

    // per-lane ldmatrix byte offsets (16x16 fragments; ks picks 32B k-half)
    const uint32_t a_l_off = (uint32_t)((lane & 15) * RSTR + (lane >> 4) * 16 + ks * 32);
    const uint32_t b_l_off = (uint32_t)(((lane & 7) + ((lane >> 4) & 1) * 8) * RSTR + ((lane >> 3) & 1) * 16 + ks * 32);

    float c0[2][2][4], c1[2][2][4];
    #pragma unroll
    for (int i = 0; i < 2; i++)
        #pragma unroll
        for (int j = 0; j < 2; j++)
            #pragma unroll
            for (int k = 0; k < 4; k++) { c0[i][j][k] = 0.0f; c1[i][j][k] = 0.0f; }

    // ---- prologue: fill buf0 with tile 0; stage x(1) in regs ----
    float4 xv = *(const float4*)xp;
    {
        uint32_t H0, M0, H1, M1;
        cvt2(xv.x, xv.y, H0, M0);
        cvt2(xv.z, xv.w, H1, M1);
        STS64(aH, H0, H1);
        STS64(aM, M0, M1);
    }
    CP_ASYNC16(bDstH, bSrcH);
    CP_ASYNC16(bDstM, bSrcM);
    CP_COMMIT();
    xv = *(const float4*)(xp + BK);
    CP_WAIT0();
    __syncthreads();   // tile 0 published

    // ---- mainloop: store tile i+1, compute tile i ----
    for (int tile = 0; tile < KT; tile++) {
        const uint32_t cur = smbase + (uint32_t)((tile & 1) * BUFG);
        const uint32_t nxtoff = (uint32_t)(((tile + 1) & 1) * BUFG);

        if (tile + 1 < KT) {
            const size_t so = (size_t)(tile + 1) * BK;
            CP_ASYNC16(bDstH + nxtoff, (const void*)(bSrcH + so));
            CP_ASYNC16(bDstM + nxtoff, (const void*)(bSrcM + so));
            CP_COMMIT();
            uint32_t H0, M0, H1, M1;
            cvt2(xv.x, xv.y, H0, M0);
            cvt2(xv.z, xv.w, H1, M1);
            STS64(aH + nxtoff, H0, H1);
            STS64(aM + nxtoff, M0, M1);
        }
        if (tile + 2 < KT) {
            xv = *(const float4*)(xp + (size_t)(tile + 2) * BK);
        }

        // ---- compute tile i (data resident since previous iteration) ----
        uint32_t ah[2][4], am[2][4], bh[2][2], bm[2][2];
        #pragma unroll
        for (int mt = 0; mt < 2; mt++) {
            uint32_t ab = cur + (uint32_t)(mt * 16 * RSTR) + a_l_off;
            ldsm4(ah[mt][0], ah[mt][1], ah[mt][2], ah[mt][3], ab + AH_OFF);
            ldsm4(am[mt][0], am[mt][1], am[mt][2], am[mt][3], ab + AM_OFF);
        }
        {
            uint32_t nb = cur + (uint32_t)(wn * RSTR) + b_l_off;
            uint32_t r0, r1, r2, r3;
            ldsm4(r0, r1, r2, r3, nb + BH_OFF);
            bh[0][0] = r0; bh[0][1] = r1; bh[1][0] = r2; bh[1][1] = r3;
            ldsm4(r0, r1, r2, r3, nb + BM_OFF);
            bm[0][0] = r0; bm[0][1] = r1; bm[1][0] = r2; bm[1][1] = r3;
        }
        #pragma unroll
        for (int mt = 0; mt < 2; mt++)
            #pragma unroll
            for (int nt = 0; nt < 2; nt++) {
                mma16816(c0[mt][nt], ah[mt], bh[nt]);
                mma16816(c1[mt][nt], ah[mt], bm[nt]);
                mma16816(c1[mt][nt], am[mt], bh[nt]);
            }

        if (tile + 1 < KT) CP_WAIT0();   // B(i+1) landed
        __syncthreads();                  // publish A/B(i+1); close compute(i)
    }

    // ---- merge k-halves into logits smem: ks0 warps write, ks1 warps add ----
    float* Lsm = reinterpret_cast<float*>(dsm);
    if (ks == 0) {
        #pragma unroll
        for (int mt = 0; mt < 2; mt++)
            #pragma unroll
            for (int nt = 0; nt < 2; nt++) {
                int r0 = mt * 16 + (lane >> 2);
                int cc = wn + nt * 8 + (lane & 3) * 2;
                Lsm[r0 * LSTR + cc]           = c0[mt][nt][0] + c1[mt][nt][0] * INVS;
                Lsm[r0 * LSTR + cc + 1]       = c0[mt][nt][1] + c1[mt][nt][1] * INVS;
                Lsm[(r0 + 8) * LSTR + cc]     = c0[mt][nt][2] + c1[mt][nt][2] * INVS;
                Lsm[(r0 + 8) * LSTR + cc + 1] = c0[mt][nt][3] + c1[mt][nt][3] * INVS;
            }
    }
    __syncthreads();
    if (ks == 1) {
        #pragma unroll
        for (int mt = 0; mt < 2; mt++)
            #pragma unroll
            for (int nt = 0; nt < 2; nt++) {
                int r0 = mt * 16 + (lane >> 2);
                int cc = wn + nt * 8 + (lane & 3) * 2;
                Lsm[r0 * LSTR + cc]           += c0[mt][nt][0] + c1[mt][nt][0] * INVS;
                Lsm[r0 * LSTR + cc + 1]       += c0[mt][nt][1] + c1[mt][nt][1] * INVS;
                Lsm[(r0 + 8) * LSTR + cc]     += c0[mt][nt][2] + c1[mt][nt][2] * INVS;
                Lsm[(r0 + 8) * LSTR + cc + 1] += c0[mt][nt][3] + c1[mt][nt][3] * INVS;
            }
    }
    __syncthreads();

    // ---- epilogue: 8 threads per token, 8 experts each ----
    const int q  = t & 7;
    const int tl = t >> 3;           // token local 0..31
    const int tok = mbase + tl;
    const float* L = &Lsm[tl * LSTR + q * 8];

    float m1 = -1e30f, m2 = -1e30f;
    int i1 = q * 8, i2 = q * 8;
    #pragma unroll
    for (int e = 0; e < 8; e++) {
        float v = L[e];
        int id = q * 8 + e;
        if (v > m1)      { m2 = m1; i2 = i1; m1 = v; i1 = id; }
        else if (v > m2) { m2 = v;  i2 = id; }
    }

    #pragma unroll
    for (int o = 1; o <= 4; o <<= 1) {
        float om1 = __shfl_xor_sync(0xffffffffu, m1, o);
        float om2 = __shfl_xor_sync(0xffffffffu, m2, o);
        int   oi1 = __shfl_xor_sync(0xffffffffu, i1, o);
        int   oi2 = __shfl_xor_sync(0xffffffffu, i2, o);
        if (ordgt(om1, oi1, m1, i1)) {
            if (ordgt(m1, i1, om2, oi2)) { m2 = m1; i2 = i1; }
            else                         { m2 = om2; i2 = oi2; }
            m1 = om1; i1 = oi1;
        } else {
            if (ordgt(om1, oi1, m2, i2)) { m2 = om1; i2 = oi1; }
        }
    }

    float ex[8];
    float Z = 0.0f;
    #pragma unroll
    for (int e = 0; e < 8; e++) {
        ex[e] = __expf(L[e] - m1);
        Z += ex[e];
    }
    Z += __shfl_xor_sync(0xffffffffu, Z, 1);
    Z += __shfl_xor_sync(0xffffffffu, Z, 2);
    Z += __shfl_xor_sync(0xffffffffu, Z, 4);
    const float invZ = 1.0f / Z;

    float ent = 0.0f;
    float4* dst = reinterpret_cast<float4*>(out + OFF_P + (size_t)tok * NEXP + q * 8);
    #pragma unroll
    for (int i = 0; i < 2; i++) {
        float p0 = ex[4*i+0] * invZ;
        float p1 = ex[4*i+1] * invZ;
        float p2 = ex[4*i+2] * invZ;
        float p3 = ex[4*i+3] * invZ;
        ent -= p0 * __logf(p0 + 1e-10f) + p1 * __logf(p1 + 1e-10f)
             + p2 * __logf(p2 + 1e-10f) + p3 * __logf(p3 + 1e-10f);
        dst[i] = make_float4(p0, p1, p2, p3);
    }
    ent += __shfl_xor_sync(0xffffffffu, ent, 1);
    ent += __shfl_xor_sync(0xffffffffu, ent, 2);
    ent += __shfl_xor_sync(0xffffffffu, ent, 4);

    float conf = 0.0f;
    if (q == 0) {
        float ed = __expf(m2 - m1);
        float w0 = 1.0f / (1.0f + ed);
        float w1 = ed * w0;
        *reinterpret_cast<float2*>(out + OFF_W + (size_t)tok * 2) = make_float2(w0, w1);
        *reinterpret_cast<float2*>(out + OFF_I + (size_t)tok * 2) = make_float2((float)i1, (float)i2);
        conf = w0;
        atomicAdd(&hist[i1], 1);
        atomicAdd(&hist[i2], 1);
    } else {
        ent = 0.0f;
    }

    #pragma unroll
    for (int o = 16; o > 0; o >>= 1) {
        ent  += __shfl_down_sync(0xffffffffu, ent,  o);
        conf += __shfl_down_sync(0xffffffffu, conf, o);
    }
    if (lane == 0) { atomicAdd(&g_ent, ent); atomicAdd(&g_conf, conf); }

    __syncthreads();
    if (t < NEXP) { int c = hist[t]; if (c) atomicAdd(&g_counts[t], c); }

    // ---- last-CTA finalize ----
    __syncthreads();
    if (t == 0) {
        __threadfence();
        s_last = (atomicAdd(&g_done, 1) == NCTAS - 1) ? 1 : 0;
    }
    __syncthreads();
    if (s_last) {
        __threadfence();
        if (t == 0) {
            out[OFF_ENT]  = atomicAdd(&g_ent,  0.0f) * (1.0f / 16384.0f);
            out[OFF_CONF] = atomicAdd(&g_conf, 0.0f) * (1.0f / 16384.0f);
        }
        if (t < NEXP)
            out[OFF_UTIL + t] = (float)atomicAdd(&g_counts[t], 0) * (1.0f / 32768.0f);
    }
}

extern "C" void kernel_launch(void* const* d_in, const int* in_sizes, int n_in,
                              void* d_out, int out_size) {
    const float* x = (const float*)d_in[0];   // [4,4096,2048] fp32
    const float* W = (const float*)d_in[1];   // [64,2048] fp32
    float* out = (float*)d_out;

    cudaFuncSetAttribute(router_kernel, cudaFuncAttributeMaxDynamicSharedMemorySize, DSM_BYTES);

    prep_kernel<<<128, 256>>>(W);
    router_kernel<<<NCTAS, NTHREADS, DSM_BYTES>>>(x, out);
}

// round 13
// speedup vs baseline: 1.1188x; 1.1188x over previous
#include <cuda_runtime.h>
#include <cuda_fp16.h>
#include <cstdint>

// ---------------- problem constants ----------------
#define T_TOKENS 16384
#define DMODEL   2048
#define NEXP     64
#define MT       64
#define NCTAS    (T_TOKENS / MT)      // 256
#define NTHREADS 256
#define BK       64                   // k per barrier period (2 x k16 per k-split warp)
#define KT       (DMODEL / BK)        // 32 iterations
#define SCALE    2048.0f
#define INVS     (1.0f / 2048.0f)

// ---------------- output layout (fp32, reference return order) ----------------
#define OFF_W    ((size_t)0)
#define OFF_I    ((size_t)32768)
#define OFF_P    ((size_t)65536)
#define OFF_ENT  ((size_t)1114112)
#define OFF_CONF ((size_t)1114113)
#define OFF_UTIL ((size_t)1114114)

// ---------------- smem layout ----------------
// rows: 128B data, 144B stride. 144/4=36 banks -> row step +4 mod 32; an 8-row
// ldmatrix phase covers banks {0,4,..,28}+4lanes = all 32 -> conflict-free.
#define RSTR     144
#define AH_OFF   0                       // A: 64 rows x 128B
#define AM_OFF   (64 * RSTR)             // 9216
#define BH_OFF   (2 * 64 * RSTR)         // 18432  B: 64 rows x 128B
#define BM_OFF   (3 * 64 * RSTR)         // 27648
#define BUFG     (4 * 64 * RSTR)         // 36864 per buffer
#define DSM_BYTES (2 * BUFG)             // 73728 (double buffer)
#define LSTR     66                       // logits row stride (floats)

// ---------------- device globals ----------------
__device__ __half g_Wh[NEXP * DMODEL];
__device__ __half g_Wm[NEXP * DMODEL];
__device__ float  g_ent;
__device__ float  g_conf;
__device__ int    g_counts[NEXP];
__device__ int    g_done;

// ---------------- helpers ----------------
__device__ __forceinline__ uint32_t smem_u32(const void* p) {
    uint32_t a;
    asm("{ .reg .u64 t; cvta.to.shared.u64 t, %1; cvt.u32.u64 %0, t; }" : "=r"(a) : "l"(p));
    return a;
}
#define STS128(addr, a, b, c, d) \
    asm volatile("st.shared.v4.b32 [%0], {%1,%2,%3,%4};" :: "r"(addr), "r"(a), "r"(b), "r"(c), "r"(d) : "memory")
#define CP_ASYNC16(dst, src) \
    asm volatile("cp.async.cg.shared.global [%0], [%1], 16;" :: "r"(dst), "l"(src) : "memory")
#define CP_COMMIT() asm volatile("cp.async.commit_group;" ::: "memory")
#define CP_WAIT0()  asm volatile("cp.async.wait_group 0;" ::: "memory")

__device__ __forceinline__ void ldsm4(uint32_t& r0, uint32_t& r1, uint32_t& r2, uint32_t& r3, uint32_t a) {
    asm volatile("ldmatrix.sync.aligned.m8n8.x4.shared.b16 {%0,%1,%2,%3}, [%4];"
                 : "=r"(r0), "=r"(r1), "=r"(r2), "=r"(r3) : "r"(a));
}
__device__ __forceinline__ void mma16816(float* c, const uint32_t* a, const uint32_t* b) {
    asm volatile("mma.sync.aligned.m16n8k16.row.col.f32.f16.f16.f32 "
                 "{%0,%1,%2,%3},{%4,%5,%6,%7},{%8,%9},{%0,%1,%2,%3};"
                 : "+f"(c[0]), "+f"(c[1]), "+f"(c[2]), "+f"(c[3])
                 : "r"(a[0]), "r"(a[1]), "r"(a[2]), "r"(a[3]), "r"(b[0]), "r"(b[1]));
}

// two-limb fp16 split of a float pair -> packed H and scaled-M half2s
__device__ __forceinline__ void cvt2(float a, float b, uint32_t& H, uint32_t& M) {
    __half2 h = __floats2half2_rn(a, b);
    float2 hf = __half22float2(h);
    __half2 m = __floats2half2_rn((a - hf.x) * SCALE, (b - hf.y) * SCALE);
    H = *reinterpret_cast<uint32_t*>(&h);
    M = *reinterpret_cast<uint32_t*>(&m);
}

// strict ordering with lowest-index tie-break (matches jax top_k)
__device__ __forceinline__ bool ordgt(float a, int ia, float b, int ib) {
    return (a > b) || (a == b && ia < ib);
}

// ---------------- prep: zero stats + split W into fp16 limbs ----------------
__global__ void prep_kernel(const float* __restrict__ W) {
    if (blockIdx.x == 0) {
        if (threadIdx.x == 0) { g_ent = 0.0f; g_conf = 0.0f; g_done = 0; }
        if (threadIdx.x < NEXP) g_counts[threadIdx.x] = 0;
    }
    int i = (blockIdx.x * 256 + threadIdx.x) * 4;
    if (i < NEXP * DMODEL) {
        float4 f = *(const float4*)(W + i);
        uint32_t h0, m0, h1, m1;
        cvt2(f.x, f.y, h0, m0);
        cvt2(f.z, f.w, h1, m1);
        *(uint2*)(g_Wh + i) = make_uint2(h0, h1);
        *(uint2*)(g_Wm + i) = make_uint2(m0, m1);
    }
}

// ---------------- main fused router ----------------
__global__ __launch_bounds__(NTHREADS, 2)
void router_kernel(const float* __restrict__ x, float* __restrict__ out) {
    extern __shared__ __align__(16) char dsm[];
    __shared__ int hist[NEXP];
    __shared__ int s_last;

    const int t    = threadIdx.x;
    const int wid  = t >> 5;
    const int lane = t & 31;
    const int mbase = blockIdx.x * MT;
    const uint32_t smbase = smem_u32(dsm);

    if (t < NEXP) hist[t] = 0;

    // A staging: row = t>>2 (0..63), 16-float quarter = t&3 of 64-k slice
    const int ar = t >> 2;
    const int aq = t & 3;
    const float* xp = x + (size_t)(mbase + ar) * DMODEL + aq * 16;
    const uint32_t aH = smbase + AH_OFF + (uint32_t)(ar * RSTR + aq * 32);
    const uint32_t aM = smbase + AM_OFF + (uint32_t)(ar * RSTR + aq * 32);

    // B cp.async: row = t>>2 (0..63), 32B quarter = t&3 per limb
    const uint32_t bDstH = smbase + BH_OFF + (uint32_t)(ar * RSTR + aq * 32);
    const uint32_t bDstM = smbase + BM_OFF + (uint32_t)(ar * RSTR + aq * 32);
    const __half* bSrcH = g_Wh + (size_t)ar * DMODEL + aq * 16;
    const __half* bSrcM = g_Wm + (size_t)ar * DMODEL + aq * 16;

    // K-specialized warps: warps 0-3 -> k-half 0, warps 4-7 -> k-half 1; 2m x 2n, M32xN32
    const int ks = wid >> 2;
    const int wq = wid & 3;
    const int wm = (wq >> 1) * 32;
    const int wn = (wq & 1) * 32;

    // per-lane ldmatrix byte offsets (ks picks 64B k-half; +32B per k16 chunk)
    const uint32_t a_l_off = (uint32_t)((lane & 15) * RSTR + (lane >> 4) * 16 + ks * 64);
    const uint32_t b_l_off = (uint32_t)(((lane & 7) + ((lane >> 4) & 1) * 8) * RSTR + ((lane >> 3) & 1) * 16 + ks * 64);

    float c0[2][4][4], c1[2][4][4];
    #pragma unroll
    for (int i = 0; i < 2; i++)
        #pragma unroll
        for (int j = 0; j < 4; j++)
            #pragma unroll
            for (int k = 0; k < 4; k++) { c0[i][j][k] = 0.0f; c1[i][j][k] = 0.0f; }

    // ---- prologue: fill buf0 with tile 0; stage x(1) in regs ----
    float4 xv0 = ((const float4*)xp)[0];
    float4 xv1 = ((const float4*)xp)[1];
    float4 xv2 = ((const float4*)xp)[2];
    float4 xv3 = ((const float4*)xp)[3];
    {
        uint32_t H[8], M[8];
        cvt2(xv0.x, xv0.y, H[0], M[0]); cvt2(xv0.z, xv0.w, H[1], M[1]);
        cvt2(xv1.x, xv1.y, H[2], M[2]); cvt2(xv1.z, xv1.w, H[3], M[3]);
        cvt2(xv2.x, xv2.y, H[4], M[4]); cvt2(xv2.z, xv2.w, H[5], M[5]);
        cvt2(xv3.x, xv3.y, H[6], M[6]); cvt2(xv3.z, xv3.w, H[7], M[7]);
        STS128(aH,      H[0], H[1], H[2], H[3]);
        STS128(aH + 16, H[4], H[5], H[6], H[7]);
        STS128(aM,      M[0], M[1], M[2], M[3]);
        STS128(aM + 16, M[4], M[5], M[6], M[7]);
    }
    CP_ASYNC16(bDstH,      bSrcH);
    CP_ASYNC16(bDstH + 16, bSrcH + 8);
    CP_ASYNC16(bDstM,      bSrcM);
    CP_ASYNC16(bDstM + 16, bSrcM + 8);
    CP_COMMIT();
    xv0 = ((const float4*)(xp + BK))[0];
    xv1 = ((const float4*)(xp + BK))[1];
    xv2 = ((const float4*)(xp + BK))[2];
    xv3 = ((const float4*)(xp + BK))[3];
    CP_WAIT0();
    __syncthreads();   // tile 0 published

    // ---- mainloop: store tile i+1, compute tile i (2 k16 chunks) ----
    for (int tile = 0; tile < KT; tile++) {
        const uint32_t cur = smbase + (uint32_t)((tile & 1) * BUFG);
        const uint32_t nxtoff = (uint32_t)(((tile + 1) & 1) * BUFG);

        if (tile + 1 < KT) {
            const size_t so = (size_t)(tile + 1) * BK;
            CP_ASYNC16(bDstH + nxtoff,      (const void*)(bSrcH + so));
            CP_ASYNC16(bDstH + nxtoff + 16, (const void*)(bSrcH + so + 8));
            CP_ASYNC16(bDstM + nxtoff,      (const void*)(bSrcM + so));
            CP_ASYNC16(bDstM + nxtoff + 16, (const void*)(bSrcM + so + 8));
            CP_COMMIT();
            uint32_t H[8], M[8];
            cvt2(xv0.x, xv0.y, H[0], M[0]); cvt2(xv0.z, xv0.w, H[1], M[1]);
            cvt2(xv1.x, xv1.y, H[2], M[2]); cvt2(xv1.z, xv1.w, H[3], M[3]);
            cvt2(xv2.x, xv2.y, H[4], M[4]); cvt2(xv2.z, xv2.w, H[5], M[5]);
            cvt2(xv3.x, xv3.y, H[6], M[6]); cvt2(xv3.z, xv3.w, H[7], M[7]);
            STS128(aH + nxtoff,      H[0], H[1], H[2], H[3]);
            STS128(aH + nxtoff + 16, H[4], H[5], H[6], H[7]);
            STS128(aM + nxtoff,      M[0], M[1], M[2], M[3]);
            STS128(aM + nxtoff + 16, M[4], M[5], M[6], M[7]);
        }
        if (tile + 2 < KT) {
            const float* xn = xp + (size_t)(tile + 2) * BK;
            xv0 = ((const float4*)xn)[0];
            xv1 = ((const float4*)xn)[1];
            xv2 = ((const float4*)xn)[2];
            xv3 = ((const float4*)xn)[3];
        }

        // ---- compute tile i: 2 k16 chunks of this warp's k-half ----
        #pragma unroll
        for (int c = 0; c < 2; c++) {
            const uint32_t coff = (uint32_t)(c * 32);
            uint32_t ah[2][4], am[2][4], bh[4][2], bm[4][2];
            #pragma unroll
            for (int mt = 0; mt < 2; mt++) {
                uint32_t ab = cur + (uint32_t)((wm + mt * 16) * RSTR) + a_l_off + coff;
                ldsm4(ah[mt][0], ah[mt][1], ah[mt][2], ah[mt][3], ab + AH_OFF);
                ldsm4(am[mt][0], am[mt][1], am[mt][2], am[mt][3], ab + AM_OFF);
            }
            #pragma unroll
            for (int np = 0; np < 2; np++) {
                uint32_t nb = cur + (uint32_t)((wn + np * 16) * RSTR) + b_l_off + coff;
                uint32_t r0, r1, r2, r3;
                ldsm4(r0, r1, r2, r3, nb + BH_OFF);
                bh[np*2][0] = r0; bh[np*2][1] = r1; bh[np*2+1][0] = r2; bh[np*2+1][1] = r3;
                ldsm4(r0, r1, r2, r3, nb + BM_OFF);
                bm[np*2][0] = r0; bm[np*2][1] = r1; bm[np*2+1][0] = r2; bm[np*2+1][1] = r3;
            }
            #pragma unroll
            for (int mt = 0; mt < 2; mt++)
                #pragma unroll
                for (int nt = 0; nt < 4; nt++) {
                    mma16816(c0[mt][nt], ah[mt], bh[nt]);
                    mma16816(c1[mt][nt], ah[mt], bm[nt]);
                    mma16816(c1[mt][nt], am[mt], bh[nt]);
                }
        }

        if (tile + 1 < KT) CP_WAIT0();   // B(i+1) landed
        __syncthreads();                  // publish A/B(i+1); close compute(i)
    }

    // ---- merge k-halves into logits smem: ks0 warps write, ks1 warps add ----
    float* Lsm = reinterpret_cast<float*>(dsm);
    if (ks == 0) {
        #pragma unroll
        for (int mt = 0; mt < 2; mt++)
            #pragma unroll
            for (int nt = 0; nt < 4; nt++) {
                int r0 = wm + mt * 16 + (lane >> 2);
                int cc = wn + nt * 8 + (lane & 3) * 2;
                Lsm[r0 * LSTR + cc]           = c0[mt][nt][0] + c1[mt][nt][0] * INVS;
                Lsm[r0 * LSTR + cc + 1]       = c0[mt][nt][1] + c1[mt][nt][1] * INVS;
                Lsm[(r0 + 8) * LSTR + cc]     = c0[mt][nt][2] + c1[mt][nt][2] * INVS;
                Lsm[(r0 + 8) * LSTR + cc + 1] = c0[mt][nt][3] + c1[mt][nt][3] * INVS;
            }
    }
    __syncthreads();
    if (ks == 1) {
        #pragma unroll
        for (int mt = 0; mt < 2; mt++)
            #pragma unroll
            for (int nt = 0; nt < 4; nt++) {
                int r0 = wm + mt * 16 + (lane >> 2);
                int cc = wn + nt * 8 + (lane & 3) * 2;
                Lsm[r0 * LSTR + cc]           += c0[mt][nt][0] + c1[mt][nt][0] * INVS;
                Lsm[r0 * LSTR + cc + 1]       += c0[mt][nt][1] + c1[mt][nt][1] * INVS;
                Lsm[(r0 + 8) * LSTR + cc]     += c0[mt][nt][2] + c1[mt][nt][2] * INVS;
                Lsm[(r0 + 8) * LSTR + cc + 1] += c0[mt][nt][3] + c1[mt][nt][3] * INVS;
            }
    }
    __syncthreads();

    // ---- epilogue: 4 threads per token, 16 experts each ----
    const int q  = t & 3;
    const int tl = t >> 2;           // token local 0..63
    const int tok = mbase + tl;
    const float* L = &Lsm[tl * LSTR + q * 16];

    float m1 = -1e30f, m2 = -1e30f;
    int i1 = q * 16, i2 = q * 16;
    #pragma unroll
    for (int e = 0; e < 16; e++) {
        float v = L[e];
        int id = q * 16 + e;
        if (v > m1)      { m2 = m1; i2 = i1; m1 = v; i1 = id; }
        else if (v > m2) { m2 = v;  i2 = id; }
    }

    #pragma unroll
    for (int o = 1; o <= 2; o <<= 1) {
        float om1 = __shfl_xor_sync(0xffffffffu, m1, o);
        float om2 = __shfl_xor_sync(0xffffffffu, m2, o);
        int   oi1 = __shfl_xor_sync(0xffffffffu, i1, o);
        int   oi2 = __shfl_xor_sync(0xffffffffu, i2, o);
        if (ordgt(om1, oi1, m1, i1)) {
            if (ordgt(m1, i1, om2, oi2)) { m2 = m1; i2 = i1; }
            else                         { m2 = om2; i2 = oi2; }
            m1 = om1; i1 = oi1;
        } else {
            if (ordgt(om1, oi1, m2, i2)) { m2 = om1; i2 = oi1; }
        }
    }

    float ex[16];
    float Z = 0.0f;
    #pragma unroll
    for (int e = 0; e < 16; e++) {
        ex[e] = __expf(L[e] - m1);
        Z += ex[e];
    }
    Z += __shfl_xor_sync(0xffffffffu, Z, 1);
    Z += __shfl_xor_sync(0xffffffffu, Z, 2);
    const float invZ = 1.0f / Z;

    float ent = 0.0f;
    float4* dst = reinterpret_cast<float4*>(out + OFF_P + (size_t)tok * NEXP + q * 16);
    #pragma unroll
    for (int i = 0; i < 4; i++) {
        float p0 = ex[4*i+0] * invZ;
        float p1 = ex[4*i+1] * invZ;
        float p2 = ex[4*i+2] * invZ;
        float p3 = ex[4*i+3] * invZ;
        ent -= p0 * __logf(p0 + 1e-10f) + p1 * __logf(p1 + 1e-10f)
             + p2 * __logf(p2 + 1e-10f) + p3 * __logf(p3 + 1e-10f);
        dst[i] = make_float4(p0, p1, p2, p3);
    }
    ent += __shfl_xor_sync(0xffffffffu, ent, 1);
    ent += __shfl_xor_sync(0xffffffffu, ent, 2);

    float conf = 0.0f;
    if (q == 0) {
        float ed = __expf(m2 - m1);
        float w0 = 1.0f / (1.0f + ed);
        float w1 = ed * w0;
        *reinterpret_cast<float2*>(out + OFF_W + (size_t)tok * 2) = make_float2(w0, w1);
        *reinterpret_cast<float2*>(out + OFF_I + (size_t)tok * 2) = make_float2((float)i1, (float)i2);
        conf = w0;
        atomicAdd(&hist[i1], 1);
        atomicAdd(&hist[i2], 1);
    } else {
        ent = 0.0f;
    }

    #pragma unroll
    for (int o = 16; o > 0; o >>= 1) {
        ent  += __shfl_down_sync(0xffffffffu, ent,  o);
        conf += __shfl_down_sync(0xffffffffu, conf, o);
    }
    if (lane == 0) { atomicAdd(&g_ent, ent); atomicAdd(&g_conf, conf); }

    __syncthreads();
    if (t < NEXP) { int c = hist[t]; if (c) atomicAdd(&g_counts[t], c); }

    // ---- last-CTA finalize ----
    __syncthreads();
    if (t == 0) {
        __threadfence();
        s_last = (atomicAdd(&g_done, 1) == NCTAS - 1) ? 1 : 0;
    }
    __syncthreads();
    if (s_last) {
        __threadfence();
        if (t == 0) {
            out[OFF_ENT]  = atomicAdd(&g_ent,  0.0f) * (1.0f / 16384.0f);
            out[OFF_CONF] = atomicAdd(&g_conf, 0.0f) * (1.0f / 16384.0f);
        }
        if (t < NEXP)
            out[OFF_UTIL + t] = (float)atomicAdd(&g_counts[t], 0) * (1.0f / 32768.0f);
    }
}

extern "C" void kernel_launch(void* const* d_in, const int* in_sizes, int n_in,
                              void* d_out, int out_size) {
    const float* x = (const float*)d_in[0];   // [4,4096,2048] fp32
    const float* W = (const float*)d_in[1];   // [64,2048] fp32
    float* out = (float*)d_out;

    cudaFuncSetAttribute(router_kernel, cudaFuncAttributeMaxDynamicSharedMemorySize, DSM_BYTES);

    prep_kernel<<<128, 256>>>(W);
    router_kernel<<<NCTAS, NTHREADS, DSM_BYTES>>>(x, out);
}

// round 14
// speedup vs baseline: 1.6764x; 1.4983x over previous
#include <cuda_runtime.h>
#include <cuda_fp16.h>
#include <cstdint>

// ---------------- problem constants ----------------
#define T_TOKENS 16384
#define DMODEL   2048
#define NEXP     64
#define MT       64
#define NCTAS    (T_TOKENS / MT)      // 256
#define NTHREADS 256
#define BK       32
#define KT       (DMODEL / BK)        // 64
#define SCALE    2048.0f
#define INVS     (1.0f / 2048.0f)

// ---------------- output layout (fp32, reference return order) ----------------
#define OFF_W    ((size_t)0)
#define OFF_I    ((size_t)32768)
#define OFF_P    ((size_t)65536)
#define OFF_ENT  ((size_t)1114112)
#define OFF_CONF ((size_t)1114113)
#define OFF_UTIL ((size_t)1114114)

// ---------------- smem stage layout (3-stage ring) ----------------
// A: raw fp32, 64 rows x 128B data, 160B stride (row step = 40 banks = +8 mod 32:
//    16-lane LDS.64 phases cover all 32 banks exactly once -> conflict-free).
// B: fp16 limbs, 64 rows x 64B data, 80B stride (proven ldmatrix-conflict-free).
#define AROWB    160
#define A_BYTES  (64 * AROWB)                // 10240
#define BH_OFF   A_BYTES                     // 10240
#define BM_OFF   (A_BYTES + 64 * 80)         // 15360
#define STAGE_BYTES (A_BYTES + 2 * 64 * 80)  // 20480
#define NSTAGE   3
#define DSM_BYTES (NSTAGE * STAGE_BYTES)     // 61440
#define BSTR     80
#define LSTR     66                          // logits row stride (floats)

// ---------------- device globals ----------------
__device__ __half g_Wh[NEXP * DMODEL];
__device__ __half g_Wm[NEXP * DMODEL];
__device__ float  g_ent;
__device__ float  g_conf;
__device__ int    g_counts[NEXP];
__device__ int    g_done;

// ---------------- helpers ----------------
__device__ __forceinline__ uint32_t smem_u32(const void* p) {
    uint32_t a;
    asm("{ .reg .u64 t; cvta.to.shared.u64 t, %1; cvt.u32.u64 %0, t; }" : "=r"(a) : "l"(p));
    return a;
}
#define CP_ASYNC16(dst, src) \
    asm volatile("cp.async.cg.shared.global [%0], [%1], 16;" :: "r"(dst), "l"(src) : "memory")
#define CP_COMMIT() asm volatile("cp.async.commit_group;" ::: "memory")
#define CP_WAIT1()  asm volatile("cp.async.wait_group 1;" ::: "memory")
#define LDS64F(f, addr) \
    asm volatile("ld.shared.v2.f32 {%0,%1}, [%2];" : "=f"((f).x), "=f"((f).y) : "r"(addr))

__device__ __forceinline__ void ldsm4(uint32_t& r0, uint32_t& r1, uint32_t& r2, uint32_t& r3, uint32_t a) {
    asm volatile("ldmatrix.sync.aligned.m8n8.x4.shared.b16 {%0,%1,%2,%3}, [%4];"
                 : "=r"(r0), "=r"(r1), "=r"(r2), "=r"(r3) : "r"(a));
}
__device__ __forceinline__ void mma16816(float* c, const uint32_t* a, const uint32_t* b) {
    asm volatile("mma.sync.aligned.m16n8k16.row.col.f32.f16.f16.f32 "
                 "{%0,%1,%2,%3},{%4,%5,%6,%7},{%8,%9},{%0,%1,%2,%3};"
                 : "+f"(c[0]), "+f"(c[1]), "+f"(c[2]), "+f"(c[3])
                 : "r"(a[0]), "r"(a[1]), "r"(a[2]), "r"(a[3]), "r"(b[0]), "r"(b[1]));
}

// two-limb fp16 split of a float pair -> packed H and scaled-M half2s
__device__ __forceinline__ void cvt2(float a, float b, uint32_t& H, uint32_t& M) {
    __half2 h = __floats2half2_rn(a, b);
    float2 hf = __half22float2(h);
    __half2 m = __floats2half2_rn((a - hf.x) * SCALE, (b - hf.y) * SCALE);
    H = *reinterpret_cast<uint32_t*>(&h);
    M = *reinterpret_cast<uint32_t*>(&m);
}

// strict ordering with lowest-index tie-break (matches jax top_k)
__device__ __forceinline__ bool ordgt(float a, int ia, float b, int ib) {
    return (a > b) || (a == b && ia < ib);
}

// ---------------- prep: zero stats + split W into fp16 limbs ----------------
__global__ void prep_kernel(const float* __restrict__ W) {
    if (blockIdx.x == 0) {
        if (threadIdx.x == 0) { g_ent = 0.0f; g_conf = 0.0f; g_done = 0; }
        if (threadIdx.x < NEXP) g_counts[threadIdx.x] = 0;
    }
    int i = (blockIdx.x * 256 + threadIdx.x) * 4;
    if (i < NEXP * DMODEL) {
        float4 f = *(const float4*)(W + i);
        uint32_t h0, m0, h1, m1;
        cvt2(f.x, f.y, h0, m0);
        cvt2(f.z, f.w, h1, m1);
        *(uint2*)(g_Wh + i) = make_uint2(h0, h1);
        *(uint2*)(g_Wm + i) = make_uint2(m0, m1);
    }
}

// ---------------- main fused router ----------------
__global__ __launch_bounds__(NTHREADS, 2)
void router_kernel(const float* __restrict__ x, float* __restrict__ out) {
    extern __shared__ __align__(16) char dsm[];
    __shared__ int hist[NEXP];
    __shared__ int s_last;

    const int t    = threadIdx.x;
    const int wid  = t >> 5;
    const int lane = t & 31;
    const int mbase = blockIdx.x * MT;
    const uint32_t smbase = smem_u32(dsm);

    if (t < NEXP) hist[t] = 0;

    // cp.async maps: row = t>>2 (0..63), chunk = t&3
    const int cr = t >> 2;
    const int cq = t & 3;
    const uint32_t aDst  = smbase + (uint32_t)(cr * AROWB + cq * 32);    // 2 x 16B
    const uint32_t bDstH = smbase + BH_OFF + (uint32_t)(cr * BSTR + cq * 16);
    const uint32_t bDstM = smbase + BM_OFF + (uint32_t)(cr * BSTR + cq * 16);
    const float*  aSrc  = x + (size_t)(mbase + cr) * DMODEL + cq * 8;
    const __half* bSrcH = g_Wh + (size_t)cr * DMODEL + cq * 8;
    const __half* bSrcM = g_Wm + (size_t)cr * DMODEL + cq * 8;

    // warps: 4m x 2k; each M16 x N64, k16 (A rows owned by exactly one warp)
    const int ks = wid >> 2;          // k16 half of the 32-k tile
    const int wq = wid & 3;           // m-warp: rows wq*16 .. +15

    // A fragment LDS addresses (fp32): row = wq*16 + (lane>>2), col = (lane&3)*2 + ks*16
    const uint32_t aL0 = (uint32_t)((wq * 16 + (lane >> 2)) * AROWB + ((lane & 3) * 2 + ks * 16) * 4);

    // B ldmatrix per-lane byte offset (same pattern as R9)
    const uint32_t b_l_off = (uint32_t)(((lane & 7) + ((lane >> 4) & 1) * 8) * BSTR
                                        + ((lane >> 3) & 1) * 16 + ks * 32);

    float c0[8][4], c1[8][4];
    #pragma unroll
    for (int j = 0; j < 8; j++)
        #pragma unroll
        for (int k = 0; k < 4; k++) { c0[j][k] = 0.0f; c1[j][k] = 0.0f; }

    // ---- prologue: issue stages 0 and 1 ----
    #pragma unroll
    for (int s = 0; s < 2; s++) {
        const uint32_t st = (uint32_t)(s * STAGE_BYTES);
        const size_t so = (size_t)s * BK;
        CP_ASYNC16(aDst + st,      (const void*)(aSrc + so));
        CP_ASYNC16(aDst + st + 16, (const void*)(aSrc + so + 4));
        CP_ASYNC16(bDstH + st, (const void*)(bSrcH + so));
        CP_ASYNC16(bDstM + st, (const void*)(bSrcM + so));
        CP_COMMIT();
    }

    int stage = 0;
    for (int tile = 0; tile < KT; tile++) {
        CP_WAIT1();        // group(tile) complete (issued 2 iterations ago)
        __syncthreads();   // stage visible to all warps; compute(tile-1) closed

        // ---- issue tile+2 into the stage freed by compute(tile-1) ----
        if (tile + 2 < KT) {
            int ns = stage + 2; if (ns >= NSTAGE) ns -= NSTAGE;
            const uint32_t st = (uint32_t)(ns * STAGE_BYTES);
            const size_t so = (size_t)(tile + 2) * BK;
            CP_ASYNC16(aDst + st,      (const void*)(aSrc + so));
            CP_ASYNC16(aDst + st + 16, (const void*)(aSrc + so + 4));
            CP_ASYNC16(bDstH + st, (const void*)(bSrcH + so));
            CP_ASYNC16(bDstM + st, (const void*)(bSrcM + so));
        }
        CP_COMMIT();       // uniform group counting (empty near tail)

        const uint32_t cur = smbase + (uint32_t)(stage * STAGE_BYTES);

        // ---- A fragment: 4 x LDS.64 fp32 -> in-register limb split (no duplication) ----
        uint32_t ah[4], am[4];
        {
            float2 f0, f1, f2, f3;
            const uint32_t a0 = cur + aL0;
            LDS64F(f0, a0);                    // (r,   c)
            LDS64F(f1, a0 + 8 * AROWB);        // (r+8, c)
            LDS64F(f2, a0 + 32);               // (r,   c+8)
            LDS64F(f3, a0 + 8 * AROWB + 32);   // (r+8, c+8)
            cvt2(f0.x, f0.y, ah[0], am[0]);
            cvt2(f1.x, f1.y, ah[1], am[1]);
            cvt2(f2.x, f2.y, ah[2], am[2]);
            cvt2(f3.x, f3.y, ah[3], am[3]);
        }

        // ---- B fragments via ldmatrix: 4 x 16-expert groups per limb ----
        uint32_t bh[8][2], bm[8][2];
        #pragma unroll
        for (int np = 0; np < 4; np++) {
            uint32_t nb = cur + (uint32_t)(np * 16 * BSTR) + b_l_off;
            uint32_t r0, r1, r2, r3;
            ldsm4(r0, r1, r2, r3, nb + BH_OFF);
            bh[np*2][0] = r0; bh[np*2][1] = r1; bh[np*2+1][0] = r2; bh[np*2+1][1] = r3;
            ldsm4(r0, r1, r2, r3, nb + BM_OFF);
            bm[np*2][0] = r0; bm[np*2][1] = r1; bm[np*2+1][0] = r2; bm[np*2+1][1] = r3;
        }

        // ---- 3 limb products, M16 x N64 ----
        #pragma unroll
        for (int nt = 0; nt < 8; nt++) {
            mma16816(c0[nt], ah, bh[nt]);
            mma16816(c1[nt], ah, bm[nt]);
            mma16816(c1[nt], am, bh[nt]);
        }

        stage++; if (stage >= NSTAGE) stage = 0;
    }

    // ---- merge k-halves into logits smem: ks0 warps write, ks1 warps add ----
    __syncthreads();   // all reads of final stage done before overlay
    float* Lsm = reinterpret_cast<float*>(dsm);
    if (ks == 0) {
        #pragma unroll
        for (int nt = 0; nt < 8; nt++) {
            int r0 = wq * 16 + (lane >> 2);
            int cc = nt * 8 + (lane & 3) * 2;
            Lsm[r0 * LSTR + cc]           = c0[nt][0] + c1[nt][0] * INVS;
            Lsm[r0 * LSTR + cc + 1]       = c0[nt][1] + c1[nt][1] * INVS;
            Lsm[(r0 + 8) * LSTR + cc]     = c0[nt][2] + c1[nt][2] * INVS;
            Lsm[(r0 + 8) * LSTR + cc + 1] = c0[nt][3] + c1[nt][3] * INVS;
        }
    }
    __syncthreads();
    if (ks == 1) {
        #pragma unroll
        for (int nt = 0; nt < 8; nt++) {
            int r0 = wq * 16 + (lane >> 2);
            int cc = nt * 8 + (lane & 3) * 2;
            Lsm[r0 * LSTR + cc]           += c0[nt][0] + c1[nt][0] * INVS;
            Lsm[r0 * LSTR + cc + 1]       += c0[nt][1] + c1[nt][1] * INVS;
            Lsm[(r0 + 8) * LSTR + cc]     += c0[nt][2] + c1[nt][2] * INVS;
            Lsm[(r0 + 8) * LSTR + cc + 1] += c0[nt][3] + c1[nt][3] * INVS;
        }
    }
    __syncthreads();

    // ---- epilogue: 4 threads per token, 16 experts each ----
    const int q  = t & 3;
    const int tl = t >> 2;           // token local 0..63
    const int tok = mbase + tl;
    const float* L = &Lsm[tl * LSTR + q * 16];

    float m1 = -1e30f, m2 = -1e30f;
    int i1 = q * 16, i2 = q * 16;
    #pragma unroll
    for (int e = 0; e < 16; e++) {
        float v = L[e];
        int id = q * 16 + e;
        if (v > m1)      { m2 = m1; i2 = i1; m1 = v; i1 = id; }
        else if (v > m2) { m2 = v;  i2 = id; }
    }

    #pragma unroll
    for (int o = 1; o <= 2; o <<= 1) {
        float om1 = __shfl_xor_sync(0xffffffffu, m1, o);
        float om2 = __shfl_xor_sync(0xffffffffu, m2, o);
        int   oi1 = __shfl_xor_sync(0xffffffffu, i1, o);
        int   oi2 = __shfl_xor_sync(0xffffffffu, i2, o);
        if (ordgt(om1, oi1, m1, i1)) {
            if (ordgt(m1, i1, om2, oi2)) { m2 = m1; i2 = i1; }
            else                         { m2 = om2; i2 = oi2; }
            m1 = om1; i1 = oi1;
        } else {
            if (ordgt(om1, oi1, m2, i2)) { m2 = om1; i2 = oi1; }
        }
    }

    float ex[16];
    float Z = 0.0f;
    #pragma unroll
    for (int e = 0; e < 16; e++) {
        ex[e] = __expf(L[e] - m1);
        Z += ex[e];
    }
    Z += __shfl_xor_sync(0xffffffffu, Z, 1);
    Z += __shfl_xor_sync(0xffffffffu, Z, 2);
    const float invZ = 1.0f / Z;

    float ent = 0.0f;
    float4* dst = reinterpret_cast<float4*>(out + OFF_P + (size_t)tok * NEXP + q * 16);
    #pragma unroll
    for (int i = 0; i < 4; i++) {
        float p0 = ex[4*i+0] * invZ;
        float p1 = ex[4*i+1] * invZ;
        float p2 = ex[4*i+2] * invZ;
        float p3 = ex[4*i+3] * invZ;
        ent -= p0 * __logf(p0 + 1e-10f) + p1 * __logf(p1 + 1e-10f)
             + p2 * __logf(p2 + 1e-10f) + p3 * __logf(p3 + 1e-10f);
        dst[i] = make_float4(p0, p1, p2, p3);
    }
    ent += __shfl_xor_sync(0xffffffffu, ent, 1);
    ent += __shfl_xor_sync(0xffffffffu, ent, 2);

    float conf = 0.0f;
    if (q == 0) {
        float ed = __expf(m2 - m1);
        float w0 = 1.0f / (1.0f + ed);
        float w1 = ed * w0;
        *reinterpret_cast<float2*>(out + OFF_W + (size_t)tok * 2) = make_float2(w0, w1);
        *reinterpret_cast<float2*>(out + OFF_I + (size_t)tok * 2) = make_float2((float)i1, (float)i2);
        conf = w0;
        atomicAdd(&hist[i1], 1);
        atomicAdd(&hist[i2], 1);
    } else {
        ent = 0.0f;
    }

    #pragma unroll
    for (int o = 16; o > 0; o >>= 1) {
        ent  += __shfl_down_sync(0xffffffffu, ent,  o);
        conf += __shfl_down_sync(0xffffffffu, conf, o);
    }
    if (lane == 0) { atomicAdd(&g_ent, ent); atomicAdd(&g_conf, conf); }

    __syncthreads();
    if (t < NEXP) { int c = hist[t]; if (c) atomicAdd(&g_counts[t], c); }

    // ---- last-CTA finalize ----
    __syncthreads();
    if (t == 0) {
        __threadfence();
        s_last = (atomicAdd(&g_done, 1) == NCTAS - 1) ? 1 : 0;
    }
    __syncthreads();
    if (s_last) {
        __threadfence();
        if (t == 0) {
            out[OFF_ENT]  = atomicAdd(&g_ent,  0.0f) * (1.0f / 16384.0f);
            out[OFF_CONF] = atomicAdd(&g_conf, 0.0f) * (1.0f / 16384.0f);
        }
        if (t < NEXP)
            out[OFF_UTIL + t] = (float)atomicAdd(&g_counts[t], 0) * (1.0f / 32768.0f);
    }
}

extern "C" void kernel_launch(void* const* d_in, const int* in_sizes, int n_in,
                              void* d_out, int out_size) {
    const float* x = (const float*)d_in[0];   // [4,4096,2048] fp32
    const float* W = (const float*)d_in[1];   // [64,2048] fp32
    float* out = (float*)d_out;

    cudaFuncSetAttribute(router_kernel, cudaFuncAttributeMaxDynamicSharedMemorySize, DSM_BYTES);

    prep_kernel<<<128, 256>>>(W);
    router_kernel<<<NCTAS, NTHREADS, DSM_BYTES>>>(x, out);
}